// round 2
// baseline (speedup 1.0000x reference)
#include <cuda_runtime.h>
#include <cstdint>

// Problem constants
#define BB 4
#define FF 60082
#define DD 256
#define KN 64
#define KH 128

// Precomputed small state
__device__ float g_v[DD];      // W_proj @ w_ff
__device__ float g_u[DD/2];    // W2 @ w_ff
__device__ float g_base[BB];   // company_out[b] + b_proj.w_ff + b_ff
__device__ float g_hb;         // b2 . w_ff

// ---------------------------------------------------------------------------
// Kernel A: tiny precompute (1 block, 256 threads)
// ---------------------------------------------------------------------------
__global__ void precompute_kernel(
    const float* __restrict__ W_proj, const float* __restrict__ w_ff,
    const float* __restrict__ W2, const float* __restrict__ b_proj,
    const float* __restrict__ b2, const float* __restrict__ b_ff,
    const float* __restrict__ theta, const int* __restrict__ com_id,
    const float* __restrict__ company_emb, const float* __restrict__ comp_table,
    const float* __restrict__ w_fc, const float* __restrict__ b_fc)
{
    __shared__ float s_wff[DD];
    int t = threadIdx.x;
    s_wff[t] = w_ff[t];
    __syncthreads();

    // v[t] = sum_j W_proj[t, j] * w_ff[j]
    float acc = 0.f;
    #pragma unroll 8
    for (int j = 0; j < DD; j++) acc += W_proj[t * DD + j] * s_wff[j];
    g_v[t] = acc;

    if (t < DD / 2) {
        float a = 0.f;
        #pragma unroll 8
        for (int j = 0; j < DD; j++) a += W2[t * DD + j] * s_wff[j];
        g_u[t] = a;
    }

    if (t == 0) {
        float c0 = 0.f, hb = 0.f;
        for (int j = 0; j < DD; j++) {
            c0 += b_proj[j] * s_wff[j];
            hb += b2[j] * s_wff[j];
        }
        g_hb = hb;
        for (int b = 0; b < BB; b++) {
            int cid = com_id[b];
            float th = theta[cid];
            float co = 0.f;
            for (int d = 0; d < DD; d++)
                co += ((1.f - th) * company_emb[b * DD + d] + th * comp_table[(size_t)cid * DD + d]) * w_fc[d];
            g_base[b] = co + b_fc[0] + c0 + b_ff[0];
        }
    }
}

// ---------------------------------------------------------------------------
// Kernel B: main stream over field_table — one warp per field row.
// out[b, f] = field_table[f] . v + g_base[b]
// ---------------------------------------------------------------------------
__global__ __launch_bounds__(256) void main_kernel(
    const float* __restrict__ field_table, float* __restrict__ out)
{
    int warp = threadIdx.x >> 5;
    int lane = threadIdx.x & 31;
    int f = blockIdx.x * 8 + warp;
    if (f >= FF) return;

    const float4* row = reinterpret_cast<const float4*>(field_table + (size_t)f * DD);
    const float4* v4  = reinterpret_cast<const float4*>(g_v);

    float4 a = row[lane];
    float4 b = row[lane + 32];
    float4 va = v4[lane];
    float4 vb = v4[lane + 32];

    float s = a.x * va.x + a.y * va.y + a.z * va.z + a.w * va.w
            + b.x * vb.x + b.y * vb.y + b.z * vb.z + b.w * vb.w;

    #pragma unroll
    for (int off = 16; off; off >>= 1)
        s += __shfl_xor_sync(0xffffffffu, s, off);

    if (lane < BB)
        out[(size_t)lane * FF + f] = s + g_base[lane];
}

// ---------------------------------------------------------------------------
// Kernel C: corrections for touched (b, f) cells.
// One 128-thread block per entry; grid = B*(KN+KH) = 768.
// Writes the final exact value (duplicates write identical values).
// ---------------------------------------------------------------------------
__device__ __forceinline__ float block_reduce128(float v, float* red)
{
    int t = threadIdx.x;
    red[t] = v;
    __syncthreads();
    #pragma unroll
    for (int s = 64; s; s >>= 1) {
        if (t < s) red[t] += red[t + s];
        __syncthreads();
    }
    float r = red[0];
    __syncthreads();
    return r;
}

__global__ __launch_bounds__(128) void corr_kernel(
    const float* __restrict__ field_table, const float* __restrict__ field_emb,
    const float* __restrict__ raw_field_embed, const float* __restrict__ W1,
    const float* __restrict__ b1, const float* __restrict__ w_ff,
    const float* __restrict__ alpha_fields,
    const int* __restrict__ now_nodes, const int* __restrict__ his_nodes,
    float* __restrict__ out)
{
    __shared__ float red[128];
    __shared__ float s_raw[DD];
    __shared__ int flag;

    int e = blockIdx.x;
    int t = threadIdx.x;
    bool isNow = (e < BB * KN);
    int b, f;
    if (isNow) { b = e / KN; f = now_nodes[e]; }
    else       { int e2 = e - BB * KN; b = e2 / KH; f = his_nodes[e2]; }

    // s[f] = field_table[f] . v
    float sv = field_table[(size_t)f * DD + t]       * g_v[t]
             + field_table[(size_t)f * DD + t + 128] * g_v[t + 128];
    float s_f = block_reduce128(sv, red);

    // membership in the *other* list for this row
    if (t == 0) flag = 0;
    __syncthreads();
    if (isNow) {
        if (his_nodes[b * KH + t] == f) flag = 1;
    } else {
        if (t < KN && now_nodes[b * KN + t] == f) flag = 1;
    }
    __syncthreads();

    bool needNow = isNow || (flag != 0);
    bool needHis = (!isNow) || (flag != 0);

    float nf = 0.f;
    if (needNow) {
        float x = field_emb[(size_t)f * DD + t]       * w_ff[t]
                + field_emb[(size_t)f * DD + t + 128] * w_ff[t + 128];
        nf = block_reduce128(x, red);
    }

    float hval = 0.f;
    if (needHis) {
        s_raw[t]       = raw_field_embed[(size_t)f * DD + t];
        s_raw[t + 128] = raw_field_embed[(size_t)f * DD + t + 128];
        __syncthreads();
        // dk = raw[f] . W1[:, t]   (W1 is (256,128) row-major)
        float dk0 = 0.f, dk1 = 0.f, dk2 = 0.f, dk3 = 0.f;
        #pragma unroll 4
        for (int d = 0; d < DD; d += 4) {
            dk0 += s_raw[d + 0] * W1[(d + 0) * 128 + t];
            dk1 += s_raw[d + 1] * W1[(d + 1) * 128 + t];
            dk2 += s_raw[d + 2] * W1[(d + 2) * 128 + t];
            dk3 += s_raw[d + 3] * W1[(d + 3) * 128 + t];
        }
        float dk = (dk0 + dk1) + (dk2 + dk3) + b1[t];
        float lv = (dk >= 0.f) ? dk : 0.01f * dk;
        hval = block_reduce128(lv * g_u[t], red) + g_hb;
    }

    if (t == 0) {
        float alpha = alpha_fields[f];
        float total = (1.f - alpha) * s_f + g_base[b];
        if (needNow) total += alpha * nf;
        if (needHis) total += alpha * hval;
        out[(size_t)b * FF + f] = total;
    }
}

// ---------------------------------------------------------------------------
extern "C" void kernel_launch(void* const* d_in, const int* in_sizes, int n_in,
                              void* d_out, int out_size)
{
    const float* company_emb     = (const float*)d_in[0];
    const float* field_emb       = (const float*)d_in[1];
    const float* raw_field_embed = (const float*)d_in[2];
    const float* comp_table      = (const float*)d_in[3];
    const float* field_table     = (const float*)d_in[4];
    const float* W_proj          = (const float*)d_in[5];
    const float* b_proj          = (const float*)d_in[6];
    const float* theta           = (const float*)d_in[7];
    const float* alpha_fields    = (const float*)d_in[8];
    const float* w_ff            = (const float*)d_in[9];
    const float* b_ff            = (const float*)d_in[10];
    const float* w_fc            = (const float*)d_in[11];
    const float* b_fc            = (const float*)d_in[12];
    const float* W1              = (const float*)d_in[13];
    const float* b1              = (const float*)d_in[14];
    const float* W2              = (const float*)d_in[15];
    const float* b2              = (const float*)d_in[16];
    const int*   now_nodes       = (const int*)d_in[17];
    const int*   his_nodes       = (const int*)d_in[18];
    const int*   com_id          = (const int*)d_in[19];

    float* out = (float*)d_out;

    precompute_kernel<<<1, 256>>>(W_proj, w_ff, W2, b_proj, b2, b_ff,
                                  theta, com_id, company_emb, comp_table,
                                  w_fc, b_fc);

    main_kernel<<<(FF + 7) / 8, 256>>>(field_table, out);

    corr_kernel<<<BB * (KN + KH), 128>>>(field_table, field_emb, raw_field_embed,
                                         W1, b1, w_ff, alpha_fields,
                                         now_nodes, his_nodes, out);
}

// round 3
// speedup vs baseline: 4.6236x; 4.6236x over previous
#include <cuda_runtime.h>
#include <cstdint>

// Problem constants
#define BB 4
#define FF 60082
#define DD 256
#define KN 64
#define KH 128

// Precomputed small state
__device__ float g_v[DD];      // W_proj @ w_ff
__device__ float g_u[DD/2];    // W2 @ w_ff
__device__ float g_base[BB];   // company_out[b] + b_proj.w_ff + b_ff + b_fc
__device__ float g_hb;         // b2 . w_ff

// ---------------------------------------------------------------------------
// Warp-coalesced 256-length dot product. All 32 lanes return the full sum.
// ---------------------------------------------------------------------------
__device__ __forceinline__ float warp_dot256(const float* __restrict__ a,
                                             const float* __restrict__ b,
                                             int lane)
{
    const float4* A = reinterpret_cast<const float4*>(a);
    const float4* B = reinterpret_cast<const float4*>(b);
    float4 x0 = A[lane], x1 = A[lane + 32];
    float4 y0 = B[lane], y1 = B[lane + 32];
    float s = x0.x * y0.x + x0.y * y0.y + x0.z * y0.z + x0.w * y0.w
            + x1.x * y1.x + x1.y * y1.y + x1.z * y1.z + x1.w * y1.w;
    #pragma unroll
    for (int off = 16; off; off >>= 1)
        s += __shfl_xor_sync(0xffffffffu, s, off);
    return s;
}

// ---------------------------------------------------------------------------
// Kernel A: precompute. One warp per dot product.
// warps 0..255    -> g_v[row]   = W_proj[row,:] . w_ff
// warps 256..383  -> g_u[row]   = W2[row,:] . w_ff
// warp  384       -> g_hb       = b2 . w_ff
// warps 385..388  -> g_base[b]
// ---------------------------------------------------------------------------
__global__ __launch_bounds__(128) void precompute_kernel(
    const float* __restrict__ W_proj, const float* __restrict__ w_ff,
    const float* __restrict__ W2, const float* __restrict__ b_proj,
    const float* __restrict__ b2, const float* __restrict__ b_ff,
    const float* __restrict__ theta, const int* __restrict__ com_id,
    const float* __restrict__ company_emb, const float* __restrict__ comp_table,
    const float* __restrict__ w_fc, const float* __restrict__ b_fc)
{
    int w = blockIdx.x * (blockDim.x >> 5) + (threadIdx.x >> 5);
    int lane = threadIdx.x & 31;

    if (w < 256) {
        float s = warp_dot256(W_proj + (size_t)w * DD, w_ff, lane);
        if (lane == 0) g_v[w] = s;
    } else if (w < 384) {
        int r = w - 256;
        float s = warp_dot256(W2 + (size_t)r * DD, w_ff, lane);
        if (lane == 0) g_u[r] = s;
    } else if (w == 384) {
        float s = warp_dot256(b2, w_ff, lane);
        if (lane == 0) g_hb = s;
    } else if (w < 385 + BB) {
        int b = w - 385;
        int cid = com_id[b];
        float th = theta[cid];
        // co = ((1-th)*company_emb[b] + th*comp_table[cid]) . w_fc
        const float4* E = reinterpret_cast<const float4*>(company_emb + (size_t)b * DD);
        const float4* T = reinterpret_cast<const float4*>(comp_table + (size_t)cid * DD);
        const float4* W = reinterpret_cast<const float4*>(w_fc);
        float s = 0.f;
        #pragma unroll
        for (int k = 0; k < 2; k++) {
            float4 e = E[lane + 32 * k];
            float4 t4 = T[lane + 32 * k];
            float4 wf = W[lane + 32 * k];
            s += ((1.f - th) * e.x + th * t4.x) * wf.x
               + ((1.f - th) * e.y + th * t4.y) * wf.y
               + ((1.f - th) * e.z + th * t4.z) * wf.z
               + ((1.f - th) * e.w + th * t4.w) * wf.w;
        }
        #pragma unroll
        for (int off = 16; off; off >>= 1)
            s += __shfl_xor_sync(0xffffffffu, s, off);
        float c0 = warp_dot256(b_proj, w_ff, lane);
        if (lane == 0) g_base[b] = s + c0 + b_fc[0] + b_ff[0];
    }
}

// ---------------------------------------------------------------------------
// Kernel B: main stream over field_table — one warp per field row.
// out[b, f] = field_table[f] . v + g_base[b]
// ---------------------------------------------------------------------------
__global__ __launch_bounds__(256) void main_kernel(
    const float* __restrict__ field_table, float* __restrict__ out)
{
    int warp = threadIdx.x >> 5;
    int lane = threadIdx.x & 31;
    int f = blockIdx.x * 8 + warp;
    if (f >= FF) return;

    const float4* row = reinterpret_cast<const float4*>(field_table + (size_t)f * DD);
    const float4* v4  = reinterpret_cast<const float4*>(g_v);

    float4 a = row[lane];
    float4 b = row[lane + 32];
    float4 va = v4[lane];
    float4 vb = v4[lane + 32];

    float s = a.x * va.x + a.y * va.y + a.z * va.z + a.w * va.w
            + b.x * vb.x + b.y * vb.y + b.z * vb.z + b.w * vb.w;

    #pragma unroll
    for (int off = 16; off; off >>= 1)
        s += __shfl_xor_sync(0xffffffffu, s, off);

    if (lane < BB)
        out[(size_t)lane * FF + f] = s + g_base[lane];
}

// ---------------------------------------------------------------------------
// Kernel C: corrections for touched (b, f) cells.
// One 128-thread block per entry; grid = B*(KN+KH) = 768.
// Writes the final exact value (duplicates write identical values).
// ---------------------------------------------------------------------------
__device__ __forceinline__ float block_reduce128(float v, float* red)
{
    int t = threadIdx.x;
    red[t] = v;
    __syncthreads();
    #pragma unroll
    for (int s = 64; s; s >>= 1) {
        if (t < s) red[t] += red[t + s];
        __syncthreads();
    }
    float r = red[0];
    __syncthreads();
    return r;
}

__global__ __launch_bounds__(128) void corr_kernel(
    const float* __restrict__ field_table, const float* __restrict__ field_emb,
    const float* __restrict__ raw_field_embed, const float* __restrict__ W1,
    const float* __restrict__ b1, const float* __restrict__ w_ff,
    const float* __restrict__ alpha_fields,
    const int* __restrict__ now_nodes, const int* __restrict__ his_nodes,
    float* __restrict__ out)
{
    __shared__ float red[128];
    __shared__ float s_raw[DD];
    __shared__ int flag;

    int e = blockIdx.x;
    int t = threadIdx.x;
    bool isNow = (e < BB * KN);
    int b, f;
    if (isNow) { b = e / KN; f = now_nodes[e]; }
    else       { int e2 = e - BB * KN; b = e2 / KH; f = his_nodes[e2]; }

    // s[f] = field_table[f] . v
    float sv = field_table[(size_t)f * DD + t]       * g_v[t]
             + field_table[(size_t)f * DD + t + 128] * g_v[t + 128];
    float s_f = block_reduce128(sv, red);

    // membership in the *other* list for this row
    if (t == 0) flag = 0;
    __syncthreads();
    if (isNow) {
        if (his_nodes[b * KH + t] == f) flag = 1;
    } else {
        if (t < KN && now_nodes[b * KN + t] == f) flag = 1;
    }
    __syncthreads();

    bool needNow = isNow || (flag != 0);
    bool needHis = (!isNow) || (flag != 0);

    float nf = 0.f;
    if (needNow) {
        float x = field_emb[(size_t)f * DD + t]       * w_ff[t]
                + field_emb[(size_t)f * DD + t + 128] * w_ff[t + 128];
        nf = block_reduce128(x, red);
    }

    float hval = 0.f;
    if (needHis) {
        s_raw[t]       = raw_field_embed[(size_t)f * DD + t];
        s_raw[t + 128] = raw_field_embed[(size_t)f * DD + t + 128];
        __syncthreads();
        // dk = raw[f] . W1[:, t]   (W1 is (256,128) row-major)
        float dk0 = 0.f, dk1 = 0.f, dk2 = 0.f, dk3 = 0.f;
        #pragma unroll 4
        for (int d = 0; d < DD; d += 4) {
            dk0 += s_raw[d + 0] * W1[(d + 0) * 128 + t];
            dk1 += s_raw[d + 1] * W1[(d + 1) * 128 + t];
            dk2 += s_raw[d + 2] * W1[(d + 2) * 128 + t];
            dk3 += s_raw[d + 3] * W1[(d + 3) * 128 + t];
        }
        float dk = (dk0 + dk1) + (dk2 + dk3) + b1[t];
        float lv = (dk >= 0.f) ? dk : 0.01f * dk;
        hval = block_reduce128(lv * g_u[t], red) + g_hb;
    }

    if (t == 0) {
        float alpha = alpha_fields[f];
        float total = (1.f - alpha) * s_f + g_base[b];
        if (needNow) total += alpha * nf;
        if (needHis) total += alpha * hval;
        out[(size_t)b * FF + f] = total;
    }
}

// ---------------------------------------------------------------------------
extern "C" void kernel_launch(void* const* d_in, const int* in_sizes, int n_in,
                              void* d_out, int out_size)
{
    const float* company_emb     = (const float*)d_in[0];
    const float* field_emb       = (const float*)d_in[1];
    const float* raw_field_embed = (const float*)d_in[2];
    const float* comp_table      = (const float*)d_in[3];
    const float* field_table     = (const float*)d_in[4];
    const float* W_proj          = (const float*)d_in[5];
    const float* b_proj          = (const float*)d_in[6];
    const float* theta           = (const float*)d_in[7];
    const float* alpha_fields    = (const float*)d_in[8];
    const float* w_ff            = (const float*)d_in[9];
    const float* b_ff            = (const float*)d_in[10];
    const float* w_fc            = (const float*)d_in[11];
    const float* b_fc            = (const float*)d_in[12];
    const float* W1              = (const float*)d_in[13];
    const float* b1              = (const float*)d_in[14];
    const float* W2              = (const float*)d_in[15];
    const float* b2              = (const float*)d_in[16];
    const int*   now_nodes       = (const int*)d_in[17];
    const int*   his_nodes       = (const int*)d_in[18];
    const int*   com_id          = (const int*)d_in[19];

    float* out = (float*)d_out;

    // 389 warps of work -> 98 blocks x 4 warps
    precompute_kernel<<<98, 128>>>(W_proj, w_ff, W2, b_proj, b2, b_ff,
                                   theta, com_id, company_emb, comp_table,
                                   w_fc, b_fc);

    main_kernel<<<(FF + 7) / 8, 256>>>(field_table, out);

    corr_kernel<<<BB * (KN + KH), 128>>>(field_table, field_emb, raw_field_embed,
                                         W1, b1, w_ff, alpha_fields,
                                         now_nodes, his_nodes, out);
}